// round 13
// baseline (speedup 1.0000x reference)
#include <cuda_runtime.h>
#include <cuda_fp16.h>
#include <cstdint>

#define T_SEQ 128
#define E_DIM 256
#define H_DIM 64

// ---- SMEM byte layout (per 256-thread CTA, total 111616 B -> 2 CTAs/SM) ----
#define SX_B    0u         // x resident, fp16 [128][256], XOR-swizzled, 512 B/row (65536)
#define SW_B    65536u     // W ring: 3 bufs x 15360 B ([192][40]h, 80 B/row) -> 111616
#define WCHUNK  15360u
// overlays (live only after phase 1):
#define QKV_B   0u         // unified QKV [128][200]h, 400 B/row (51200)
#define SP_B    51200u     // P [128][136]h, 272 B/row (34816)
#define PM_B    86016u     // float[4][128]
#define PS_B    88064u     // float[4][128]
#define SMEM_BYTES 111616u

#define LDX   512          // x row stride (bytes)
#define LDW   80           // W chunk row stride
#define LDQ   400          // QKV row stride
#define LDP   272          // P row stride

// log2(e)/8  (softmax in log2 domain; 1/sqrt(64) folded in)
#define SCL 0.18033688f

// W pre-converted fp16: 8 chunks (k32 each) x [192 rows n][40 halves k(32)+pad]
__device__ __align__(16) __half g_wt[8 * 192 * 40];

// ---------------- helpers ----------------
__device__ __forceinline__ uint32_t smem_u32(const void* p) {
    uint32_t a;
    asm("{ .reg .u64 t; cvta.to.shared.u64 t, %1; cvt.u32.u64 %0, t; }" : "=r"(a) : "l"(p));
    return a;
}
__device__ __forceinline__ uint32_t pack2(float lo, float hi) {
    uint32_t r;
    asm("cvt.rn.f16x2.f32 %0, %1, %2;" : "=r"(r) : "f"(hi), "f"(lo));  // first src -> high
    return r;
}
__device__ __forceinline__ float fex2(float x) {
    float r;
    asm("ex2.approx.f32 %0, %1;" : "=f"(r) : "f"(x));
    return r;
}
#define LDSM_X4(R, a) \
    asm volatile("ldmatrix.sync.aligned.m8n8.x4.shared.b16 {%0,%1,%2,%3}, [%4];" \
        : "=r"((R)[0]), "=r"((R)[1]), "=r"((R)[2]), "=r"((R)[3]) : "r"(a))
#define LDSM_X4T(R, a) \
    asm volatile("ldmatrix.sync.aligned.m8n8.x4.trans.shared.b16 {%0,%1,%2,%3}, [%4];" \
        : "=r"((R)[0]), "=r"((R)[1]), "=r"((R)[2]), "=r"((R)[3]) : "r"(a))
#define MMA16816(D, A, B0, B1) \
    asm volatile("mma.sync.aligned.m16n8k16.row.col.f32.f16.f16.f32 " \
        "{%0,%1,%2,%3}, {%4,%5,%6,%7}, {%8,%9}, {%0,%1,%2,%3};" \
        : "+f"((D)[0]), "+f"((D)[1]), "+f"((D)[2]), "+f"((D)[3]) \
        : "r"((A)[0]), "r"((A)[1]), "r"((A)[2]), "r"((A)[3]), "r"(B0), "r"(B1))
#define CP_ASYNC16(dst, src) \
    asm volatile("cp.async.cg.shared.global [%0], [%1], 16;" :: "r"(dst), "l"(src))
#define CP_COMMIT()  asm volatile("cp.async.commit_group;" ::: "memory")
#define CP_WAITN(n)  asm volatile("cp.async.wait_group %0;" :: "n"(n) : "memory")

// fetch W chunk c into ring buffer slot s (each fetch = one commit group)
#define FETCH_W(c, s) do {                                                     \
    const char* _ws = reinterpret_cast<const char*>(g_wt) + (c) * WCHUNK;      \
    _Pragma("unroll")                                                          \
    for (int _i = 0; _i < 4; _i++) {                                           \
        int _idx = tid + _i * 256;                                             \
        if (_idx < 960)                                                        \
            CP_ASYNC16(sbase + SW_B + (s) * WCHUNK + _idx * 16, _ws + _idx * 16); \
    }                                                                          \
    CP_COMMIT();                                                               \
} while (0)

// ---------------- W prep: fp32 [E][H] -> fp16 chunks [ec2(8)][n(192)][40] ----------------
__global__ void prep_w_kernel(const float* __restrict__ Wq,
                              const float* __restrict__ Wk,
                              const float* __restrict__ Wv) {
    int ec2 = blockIdx.x;             // 0..7, k-chunk of 32
#pragma unroll
    for (int i = 0; i < 30; i++) {
        int idx = threadIdx.x + i * 256;      // 0..7679
        int n = idx / 40, k = idx % 40;
        __half v = __float2half_rn(0.f);
        if (k < 32) {
            int m = n >> 6, h = n & 63;
            const float* W = (m == 0) ? Wq : (m == 1) ? Wk : Wv;
            v = __float2half_rn(W[(ec2 * 32 + k) * H_DIM + h]);
        }
        g_wt[(size_t)ec2 * 7680 + idx] = v;
    }
}

// ---------------- main kernel: 256 threads, 8 warps, 2 CTAs/SM ----------------
__global__ __launch_bounds__(256, 2)
void attn_fp16_kernel(const float* __restrict__ x, float* __restrict__ out) {
    extern __shared__ char smem[];
    const uint32_t sbase = smem_u32(smem);
    const int tid = threadIdx.x, warp = tid >> 5, lane = tid & 31;
    const int g = lane >> 2, t = lane & 3;
    const int w01 = warp & 1, w03 = warp >> 1;   // 2 x 4 warp grid
    const size_t b = blockIdx.x;
    const float* xb = x + b * (size_t)(T_SEQ * E_DIM);

    // =============== Phase 1: QKV = x @ Wt (x resident, W ring, 2 M-passes) ===============
    FETCH_W(0, 0);
    FETCH_W(1, 1);
    // stage x: fp32 -> fp16, XOR-swizzled [128][256]h
#pragma unroll
    for (int i = 0; i < 16; i++) {
        int q = tid + i * 256;            // 0..4095 16B-groups
        int row = q >> 5, grp = q & 31;
        const float* p = xb + row * E_DIM + grp * 8;
        float4 f0 = *reinterpret_cast<const float4*>(p);
        float4 f1 = *reinterpret_cast<const float4*>(p + 4);
        uint4 u;
        u.x = pack2(f0.x, f0.y);  u.y = pack2(f0.z, f0.w);
        u.z = pack2(f1.x, f1.y);  u.w = pack2(f1.z, f1.w);
        *reinterpret_cast<uint4*>(smem + SX_B + row * LDX + ((grp ^ (row & 7)) * 16)) = u;
    }
    CP_WAITN(1);
    __syncthreads();

    float acc1[2][6][4];
#pragma unroll
    for (int i = 0; i < 2; i++)
#pragma unroll
        for (int j = 0; j < 6; j++)
#pragma unroll
            for (int r = 0; r < 4; r++) acc1[i][j][r] = 0.f;

    const int n0 = w03 * 48;
    const uint32_t boff = (uint32_t)(n0 + ((lane >> 4) << 3) + (lane & 7)) * LDW
                        + ((lane >> 3) & 1) * 16;

#pragma unroll
    for (int u = 0; u < 16; u++) {           // 8 k32-chunks x 2 M-passes
        if (u >= 1) __syncthreads();
        if (u == 8) {
            // ---- pass-0 epilogue: rows 0..63 -> QKV (bytes < 25600; x rows 64+ untouched) ----
#pragma unroll
            for (int mt = 0; mt < 2; mt++) {
                int rlo = w01 * 32 + mt * 16 + g, rhi = rlo + 8;
#pragma unroll
                for (int nt = 0; nt < 6; nt++) {
                    int cg = n0 + nt * 8 + t * 2;
                    *reinterpret_cast<uint32_t*>(smem + QKV_B + rlo * LDQ + cg * 2) =
                        pack2(acc1[mt][nt][0], acc1[mt][nt][1]);
                    *reinterpret_cast<uint32_t*>(smem + QKV_B + rhi * LDQ + cg * 2) =
                        pack2(acc1[mt][nt][2], acc1[mt][nt][3]);
                }
            }
#pragma unroll
            for (int i = 0; i < 2; i++)
#pragma unroll
                for (int j = 0; j < 6; j++)
#pragma unroll
                    for (int r = 0; r < 4; r++) acc1[i][j][r] = 0.f;
        }
        if (u + 2 < 16) FETCH_W((u + 2) & 7, (u + 2) % 3);
        if (u < 14) { CP_WAITN(2); } else if (u == 14) { CP_WAITN(1); } else { CP_WAITN(0); }

        const int pass = u >> 3, ec2 = u & 7;
        const int m0p = pass * 64 + w01 * 32;
        const uint32_t wb = sbase + SW_B + (u % 3) * WCHUNK + boff;
#pragma unroll
        for (int kt = 0; kt < 2; kt++) {
            uint32_t a[2][4], bf[3][4];
#pragma unroll
            for (int mt = 0; mt < 2; mt++) {
                int row = m0p + mt * 16 + (lane & 15);
                int grp = (ec2 * 4 + kt * 2 + (lane >> 4)) ^ (row & 7);
                LDSM_X4(a[mt], sbase + SX_B + row * LDX + grp * 16);
            }
#pragma unroll
            for (int bt = 0; bt < 3; bt++) LDSM_X4(bf[bt], wb + bt * 16 * LDW + kt * 32);
#pragma unroll
            for (int mt = 0; mt < 2; mt++)
#pragma unroll
                for (int nt = 0; nt < 6; nt++)
                    MMA16816(acc1[mt][nt], a[mt], bf[nt >> 1][(nt & 1) * 2],
                             bf[nt >> 1][(nt & 1) * 2 + 1]);
        }
    }
    __syncthreads();
    // ---- pass-1 epilogue: rows 64..127 ----
#pragma unroll
    for (int mt = 0; mt < 2; mt++) {
        int rlo = 64 + w01 * 32 + mt * 16 + g, rhi = rlo + 8;
#pragma unroll
        for (int nt = 0; nt < 6; nt++) {
            int cg = n0 + nt * 8 + t * 2;
            *reinterpret_cast<uint32_t*>(smem + QKV_B + rlo * LDQ + cg * 2) =
                pack2(acc1[mt][nt][0], acc1[mt][nt][1]);
            *reinterpret_cast<uint32_t*>(smem + QKV_B + rhi * LDQ + cg * 2) =
                pack2(acc1[mt][nt][2], acc1[mt][nt][3]);
        }
    }
    __syncthreads();

    // =============== Phase 2a: S = Q @ K^T, causal softmax -> P ===============
    const int m0 = w01 * 64, n02 = w03 * 32;
    const bool active = (n02 <= m0 + 63);
    float acc2[4][4][4];
    float* pm = reinterpret_cast<float*>(smem + PM_B);
    float* ps = reinterpret_cast<float*>(smem + PS_B);
    float fscale[4][2];

    if (active) {
#pragma unroll
        for (int i = 0; i < 4; i++)
#pragma unroll
            for (int j = 0; j < 4; j++)
#pragma unroll
                for (int r = 0; r < 4; r++) acc2[i][j][r] = 0.f;

        const uint32_t arow = sbase + QKV_B + (m0 + (lane & 15)) * LDQ + (lane >> 4) * 16;
        const uint32_t brow = sbase + QKV_B + (n02 + ((lane >> 4) << 3) + (lane & 7)) * LDQ
                            + 128 + ((lane >> 3) & 1) * 16;
#pragma unroll
        for (int kt = 0; kt < 4; kt++) {
            uint32_t a[4][4], bf[2][4];
#pragma unroll
            for (int mt = 0; mt < 4; mt++) LDSM_X4(a[mt], arow + mt * 16 * LDQ + kt * 32);
#pragma unroll
            for (int bt = 0; bt < 2; bt++) LDSM_X4(bf[bt], brow + bt * 16 * LDQ + kt * 32);
#pragma unroll
            for (int mt = 0; mt < 4; mt++)
#pragma unroll
                for (int nt = 0; nt < 4; nt++)
                    MMA16816(acc2[mt][nt], a[mt], bf[nt >> 1][(nt & 1) * 2],
                             bf[nt >> 1][(nt & 1) * 2 + 1]);
        }

        // mask + local (32-col chunk) softmax partials (log2 domain)
#pragma unroll
        for (int mt = 0; mt < 4; mt++) {
            int rlo = m0 + mt * 16 + g, rhi = rlo + 8;
            float mlo = -1e30f, mhi = -1e30f;
#pragma unroll
            for (int nt = 0; nt < 4; nt++)
#pragma unroll
                for (int j = 0; j < 2; j++) {
                    int c = n02 + nt * 8 + t * 2 + j;
                    float v0 = acc2[mt][nt][j] * SCL;
                    v0 = (c <= rlo) ? v0 : -1e30f;
                    acc2[mt][nt][j] = v0; mlo = fmaxf(mlo, v0);
                    float v1 = acc2[mt][nt][2 + j] * SCL;
                    v1 = (c <= rhi) ? v1 : -1e30f;
                    acc2[mt][nt][2 + j] = v1; mhi = fmaxf(mhi, v1);
                }
            mlo = fmaxf(mlo, __shfl_xor_sync(0xffffffffu, mlo, 1));
            mlo = fmaxf(mlo, __shfl_xor_sync(0xffffffffu, mlo, 2));
            mhi = fmaxf(mhi, __shfl_xor_sync(0xffffffffu, mhi, 1));
            mhi = fmaxf(mhi, __shfl_xor_sync(0xffffffffu, mhi, 2));
            float slo = 0.f, shi = 0.f;
#pragma unroll
            for (int nt = 0; nt < 4; nt++)
#pragma unroll
                for (int j = 0; j < 2; j++) {
                    float e0 = fex2(acc2[mt][nt][j] - mlo);
                    float e1 = fex2(acc2[mt][nt][2 + j] - mhi);
                    acc2[mt][nt][j] = e0;  acc2[mt][nt][2 + j] = e1;
                    slo += e0; shi += e1;
                }
            slo += __shfl_xor_sync(0xffffffffu, slo, 1);
            slo += __shfl_xor_sync(0xffffffffu, slo, 2);
            shi += __shfl_xor_sync(0xffffffffu, shi, 1);
            shi += __shfl_xor_sync(0xffffffffu, shi, 2);
            if (t == 0) {
                pm[w03 * 128 + rlo] = mlo;  pm[w03 * 128 + rhi] = mhi;
                ps[w03 * 128 + rlo] = slo;  ps[w03 * 128 + rhi] = shi;
            }
            fscale[mt][0] = mlo;  fscale[mt][1] = mhi;
        }
    } else {
        if (t == 0) {
#pragma unroll
            for (int mt = 0; mt < 4; mt++) {
                int rlo = m0 + mt * 16 + g, rhi = rlo + 8;
                pm[w03 * 128 + rlo] = -1e30f;  pm[w03 * 128 + rhi] = -1e30f;
                ps[w03 * 128 + rlo] = 0.f;     ps[w03 * 128 + rhi] = 0.f;
            }
        }
    }
    __syncthreads();

    // combine partials, write P (fp16); inactive tiles never read by kt-skipped PV
    if (active) {
#pragma unroll
        for (int mt = 0; mt < 4; mt++) {
            int rlo = m0 + mt * 16 + g, rhi = rlo + 8;
            float M0 = pm[rlo], M1 = pm[128 + rlo], M2 = pm[256 + rlo], M3 = pm[384 + rlo];
            float Mlo = fmaxf(fmaxf(M0, M1), fmaxf(M2, M3));
            float Zlo = ps[rlo] * fex2(M0 - Mlo) + ps[128 + rlo] * fex2(M1 - Mlo)
                      + ps[256 + rlo] * fex2(M2 - Mlo) + ps[384 + rlo] * fex2(M3 - Mlo);
            float N0 = pm[rhi], N1 = pm[128 + rhi], N2 = pm[256 + rhi], N3 = pm[384 + rhi];
            float Mhi = fmaxf(fmaxf(N0, N1), fmaxf(N2, N3));
            float Zhi = ps[rhi] * fex2(N0 - Mhi) + ps[128 + rhi] * fex2(N1 - Mhi)
                      + ps[256 + rhi] * fex2(N2 - Mhi) + ps[384 + rhi] * fex2(N3 - Mhi);
            float flo = fex2(fscale[mt][0] - Mlo) / Zlo;
            float fhi = fex2(fscale[mt][1] - Mhi) / Zhi;
#pragma unroll
            for (int nt = 0; nt < 4; nt++) {
                int c = n02 + nt * 8 + t * 2;
                *reinterpret_cast<uint32_t*>(smem + SP_B + rlo * LDP + c * 2) =
                    pack2(acc2[mt][nt][0] * flo, acc2[mt][nt][1] * flo);
                *reinterpret_cast<uint32_t*>(smem + SP_B + rhi * LDP + c * 2) =
                    pack2(acc2[mt][nt][2] * fhi, acc2[mt][nt][3] * fhi);
            }
        }
    }
    __syncthreads();

    // =============== Phase 2c: O = P @ V  (causal kt-skip) ===============
    const int n03 = w03 * 16;
    float acc3[4][2][4];
#pragma unroll
    for (int i = 0; i < 4; i++)
#pragma unroll
        for (int j = 0; j < 2; j++)
#pragma unroll
            for (int r = 0; r < 4; r++) acc3[i][j][r] = 0.f;

    const uint32_t prow = sbase + SP_B + (m0 + (lane & 15)) * LDP + (lane >> 4) * 16;
    const uint32_t vbase = sbase + QKV_B
                         + (((lane >> 3) & 1) * 8 + (lane & 7)) * LDQ
                         + 256 + (lane >> 4) * 16 + n03 * 2;
    const int ktend = 4 + 4 * w01;     // P cols beyond m0+63 are exactly zero
#pragma unroll 4
    for (int kt = 0; kt < ktend; kt++) {
        uint32_t a3[4][4], bv[4];
#pragma unroll
        for (int mt = 0; mt < 4; mt++) LDSM_X4(a3[mt], prow + mt * 16 * LDP + kt * 32);
        LDSM_X4T(bv, vbase + kt * 16 * LDQ);
#pragma unroll
        for (int mt = 0; mt < 4; mt++) {
            MMA16816(acc3[mt][0], a3[mt], bv[0], bv[1]);
            MMA16816(acc3[mt][1], a3[mt], bv[2], bv[3]);
        }
    }

    // output: fp32 float2 stores
    float* ob = out + b * (size_t)(T_SEQ * H_DIM);
#pragma unroll
    for (int mt = 0; mt < 4; mt++) {
        int rlo = m0 + mt * 16 + g, rhi = rlo + 8;
#pragma unroll
        for (int nt = 0; nt < 2; nt++) {
            int c = n03 + nt * 8 + t * 2;
            *reinterpret_cast<float2*>(ob + rlo * H_DIM + c) =
                make_float2(acc3[mt][nt][0], acc3[mt][nt][1]);
            *reinterpret_cast<float2*>(ob + rhi * H_DIM + c) =
                make_float2(acc3[mt][nt][2], acc3[mt][nt][3]);
        }
    }
}

extern "C" void kernel_launch(void* const* d_in, const int* in_sizes, int n_in,
                              void* d_out, int out_size) {
    const float* x  = (const float*)d_in[0];
    const float* Wq = (const float*)d_in[1];
    const float* Wk = (const float*)d_in[2];
    const float* Wv = (const float*)d_in[3];
    float* out = (float*)d_out;

    int B = in_sizes[0] / (T_SEQ * E_DIM);   // 4096

    cudaFuncSetAttribute(attn_fp16_kernel,
                         cudaFuncAttributeMaxDynamicSharedMemorySize,
                         (int)SMEM_BYTES);

    prep_w_kernel<<<8, 256>>>(Wq, Wk, Wv);
    attn_fp16_kernel<<<B, 256, SMEM_BYTES>>>(x, out);
}